// round 7
// baseline (speedup 1.0000x reference)
#include <cuda_runtime.h>
#include <cstdint>
#include <cstddef>

// Problem constants (fixed by setup_inputs).
#define B_Q    256
#define N_BANK 50000
#define DIM_S  4096
#define DIM_D  2048
#define KTOP   9

// ---------------- static device scratch (no allocations allowed) -------------
__device__ __align__(128) float g_scores[(size_t)B_Q * N_BANK];   // 51.2 MB, reused per branch
__device__ __align__(128) float g_inv_sem[N_BANK];
__device__ __align__(128) float g_inv_dst[N_BANK];
__device__ __align__(128) float g_partial[B_Q];

// ---------------- packed fp32x2 helpers (sm_103a FFMA2 path) -----------------
__device__ __forceinline__ unsigned long long pk2(float lo, float hi) {
    unsigned long long r;
    asm("mov.b64 %0, {%1, %2};" : "=l"(r) : "f"(lo), "f"(hi));
    return r;
}
__device__ __forceinline__ void ffma2(unsigned long long& c,
                                      unsigned long long a,
                                      unsigned long long b) {
    asm("fma.rn.f32x2 %0, %1, %2, %0;" : "+l"(c) : "l"(a), "l"(b));
}
__device__ __forceinline__ float2 upk2(unsigned long long x) {
    float2 f;
    asm("mov.b64 {%0, %1}, %2;" : "=f"(f.x), "=f"(f.y) : "l"(x));
    return f;
}

// ---------------- 1) bank row inverse norms (both banks, one launch) ---------
__global__ void norm_kernel(const float* __restrict__ sem_bank,
                            const float* __restrict__ dst_bank) {
    int gwarp = (blockIdx.x * blockDim.x + threadIdx.x) >> 5;
    int lane  = threadIdx.x & 31;
    const float* bank;
    float* outp;
    int D, row;
    if (gwarp < N_BANK)          { bank = sem_bank; outp = g_inv_sem; D = DIM_S; row = gwarp; }
    else if (gwarp < 2 * N_BANK) { bank = dst_bank; outp = g_inv_dst; D = DIM_D; row = gwarp - N_BANK; }
    else return;

    const float4* r4 = reinterpret_cast<const float4*>(bank + (size_t)row * D);
    float s = 0.f;
    int nv = D >> 2;
    for (int i = lane; i < nv; i += 32) {
        float4 v = r4[i];
        s += v.x * v.x + v.y * v.y + v.z * v.z + v.w * v.w;
    }
    #pragma unroll
    for (int o = 16; o; o >>= 1) s += __shfl_xor_sync(0xffffffffu, s, o);
    if (lane == 0) outp[row] = rsqrtf(s);
}

// ---------------- 2) fp32 GEMM with fused invnorm epilogue -------------------
// C[m, n] = (sum_k A[m,k] * Bank[n,k]) * inv[n],  M=256, N=50000, K in {4096,2048}
// Tile: 128(M) x 128(N) x 8(K), 256 threads, 8x8 per thread (4+4 column split
// so stores are contiguous float4 across a half-warp).
#define BM  128
#define BN  128
#define BKK 8

__global__ __launch_bounds__(256, 2)
void gemm_score_kernel(const float* __restrict__ A,
                       const float* __restrict__ Bank,
                       int which,     // 0 = semantic, 1 = distorsion
                       int K)
{
    __shared__ float As[BKK][BM];
    __shared__ float Bs[BKK][BN];

    const float* __restrict__ inv = which ? g_inv_dst : g_inv_sem;
    float* __restrict__ C = g_scores;

    const int tid = threadIdx.x;
    const int m0  = blockIdx.y * BM;
    const int n0  = blockIdx.x * BN;

    // loader mapping: thread -> (row, k4) inside 128x8 tile, one float4 each
    const int lrow = tid >> 1;
    const int lk   = (tid & 1) << 2;

    // compute mapping: 16x16 thread grid
    const int tm = tid >> 4;   // 0..15 -> rows tm*8 .. tm*8+7
    const int tn = tid & 15;   // 0..15 -> cols tn*4..+3 and 64+tn*4..+3

    const bool brow_ok = (n0 + lrow) < N_BANK;
    const float* Ap = A    + (size_t)(m0 + lrow) * K + lk;
    const float* Bp = Bank + (size_t)(brow_ok ? (n0 + lrow) : 0) * K + lk;

    unsigned long long acc[8][4];
    #pragma unroll
    for (int i = 0; i < 8; i++)
        #pragma unroll
        for (int j = 0; j < 4; j++) acc[i][j] = 0ULL;

    for (int k0 = 0; k0 < K; k0 += BKK) {
        float4 av = *reinterpret_cast<const float4*>(Ap + k0);
        float4 bv = make_float4(0.f, 0.f, 0.f, 0.f);
        if (brow_ok) bv = *reinterpret_cast<const float4*>(Bp + k0);

        As[lk + 0][lrow] = av.x; As[lk + 1][lrow] = av.y;
        As[lk + 2][lrow] = av.z; As[lk + 3][lrow] = av.w;
        Bs[lk + 0][lrow] = bv.x; Bs[lk + 1][lrow] = bv.y;
        Bs[lk + 2][lrow] = bv.z; Bs[lk + 3][lrow] = bv.w;
        __syncthreads();

        #pragma unroll
        for (int kk = 0; kk < BKK; kk++) {
            float4 a0 = *reinterpret_cast<const float4*>(&As[kk][tm * 8]);
            float4 a1 = *reinterpret_cast<const float4*>(&As[kk][tm * 8 + 4]);
            float4 b0 = *reinterpret_cast<const float4*>(&Bs[kk][tn * 4]);
            float4 b1 = *reinterpret_cast<const float4*>(&Bs[kk][64 + tn * 4]);

            unsigned long long bp0 = pk2(b0.x, b0.y);
            unsigned long long bp1 = pk2(b0.z, b0.w);
            unsigned long long bp2 = pk2(b1.x, b1.y);
            unsigned long long bp3 = pk2(b1.z, b1.w);
            float a[8] = {a0.x, a0.y, a0.z, a0.w, a1.x, a1.y, a1.z, a1.w};

            #pragma unroll
            for (int i = 0; i < 8; i++) {
                unsigned long long ad = pk2(a[i], a[i]);
                ffma2(acc[i][0], ad, bp0);
                ffma2(acc[i][1], ad, bp1);
                ffma2(acc[i][2], ad, bp2);
                ffma2(acc[i][3], ad, bp3);
            }
        }
        __syncthreads();
    }

    // epilogue: scale by bank inverse norm, store scores
    const int c0 = n0 + tn * 4;
    const int c1 = n0 + 64 + tn * 4;
    float w0[4], w1[4];
    #pragma unroll
    for (int j = 0; j < 4; j++) {
        w0[j] = (c0 + j < N_BANK) ? inv[c0 + j] : 0.f;
        w1[j] = (c1 + j < N_BANK) ? inv[c1 + j] : 0.f;
    }
    #pragma unroll
    for (int i = 0; i < 8; i++) {
        const int r = m0 + tm * 8 + i;
        float* cp = C + (size_t)r * N_BANK;
        float2 p0 = upk2(acc[i][0]); float2 p1 = upk2(acc[i][1]);
        float2 p2 = upk2(acc[i][2]); float2 p3 = upk2(acc[i][3]);
        float o0[4] = { p0.x * w0[0], p0.y * w0[1], p1.x * w0[2], p1.y * w0[3] };
        float o1[4] = { p2.x * w1[0], p2.y * w1[1], p3.x * w1[2], p3.y * w1[3] };
        if (c0 + 3 < N_BANK) {
            *reinterpret_cast<float4*>(cp + c0) = make_float4(o0[0], o0[1], o0[2], o0[3]);
        } else {
            #pragma unroll
            for (int j = 0; j < 4; j++) if (c0 + j < N_BANK) cp[c0 + j] = o0[j];
        }
        if (c1 + 3 < N_BANK) {
            *reinterpret_cast<float4*>(cp + c1) = make_float4(o1[0], o1[1], o1[2], o1[3]);
        } else {
            #pragma unroll
            for (int j = 0; j < 4; j++) if (c1 + j < N_BANK) cp[c1 + j] = o1[j];
        }
    }
}

// ---------------- 3) top-9 per row + metrics gather --------------------------
__device__ __forceinline__ void ins9(float s, int n, float v[KTOP], int id[KTOP]) {
    if (s <= v[KTOP - 1]) return;
    v[KTOP - 1]  = s;
    id[KTOP - 1] = n;
    #pragma unroll
    for (int q = KTOP - 1; q > 0; q--) {
        if (v[q] > v[q - 1]) {
            float tv = v[q]; v[q] = v[q - 1]; v[q - 1] = tv;
            int   ti = id[q]; id[q] = id[q - 1]; id[q - 1] = ti;
        }
    }
}

__global__ void topk_kernel(const float* __restrict__ metrics,
                            float* __restrict__ out,
                            int phase)   // 0: write g_partial; 1: finalize out
{
    __shared__ float sv[256 * KTOP];
    __shared__ int   si[256 * KTOP];
    __shared__ float sv2[32 * KTOP];
    __shared__ int   si2[32 * KTOP];

    const int b   = blockIdx.x;
    const int tid = threadIdx.x;
    const float* row = g_scores + (size_t)b * N_BANK;

    float v[KTOP]; int id[KTOP];
    #pragma unroll
    for (int i = 0; i < KTOP; i++) { v[i] = -3.402823466e38f; id[i] = 0; }

    for (int n = tid; n < N_BANK; n += 256) ins9(row[n], n, v, id);

    #pragma unroll
    for (int i = 0; i < KTOP; i++) { sv[tid * KTOP + i] = v[i]; si[tid * KTOP + i] = id[i]; }
    __syncthreads();

    if (tid < 32) {
        float mv[KTOP]; int mi[KTOP];
        #pragma unroll
        for (int i = 0; i < KTOP; i++) { mv[i] = -3.402823466e38f; mi[i] = 0; }
        for (int t = tid * 8; t < tid * 8 + 8; t++)
            for (int i = 0; i < KTOP; i++)
                ins9(sv[t * KTOP + i], si[t * KTOP + i], mv, mi);
        #pragma unroll
        for (int i = 0; i < KTOP; i++) { sv2[tid * KTOP + i] = mv[i]; si2[tid * KTOP + i] = mi[i]; }
    }
    __syncthreads();

    if (tid == 0) {
        float mv[KTOP]; int mi[KTOP];
        #pragma unroll
        for (int i = 0; i < KTOP; i++) { mv[i] = -3.402823466e38f; mi[i] = 0; }
        for (int t = 0; t < 32; t++)
            for (int i = 0; i < KTOP; i++)
                ins9(sv2[t * KTOP + i], si2[t * KTOP + i], mv, mi);
        float ssum = 0.f;
        #pragma unroll
        for (int i = 0; i < KTOP; i++) ssum += metrics[mi[i]];
        if (phase == 0) g_partial[b] = ssum;
        else            out[b] = (g_partial[b] + ssum) * (1.f / (2.f * KTOP));
    }
}

// ---------------- launch ------------------------------------------------------
extern "C" void kernel_launch(void* const* d_in, const int* in_sizes, int n_in,
                              void* d_out, int out_size) {
    // Identify inputs by element count (all distinct), robust to metadata order.
    const float* f_content    = nullptr;
    const float* f_distorsion = nullptr;
    const float* sem_bank     = nullptr;
    const float* dst_bank     = nullptr;
    const float* metrics      = nullptr;
    for (int i = 0; i < n_in; i++) {
        switch (in_sizes[i]) {
            case B_Q * DIM_S:            f_content    = (const float*)d_in[i]; break; // 1,048,576
            case B_Q * DIM_D:            f_distorsion = (const float*)d_in[i]; break; //   524,288
            case N_BANK * DIM_S:         sem_bank     = (const float*)d_in[i]; break; // 204,800,000
            case N_BANK * DIM_D:         dst_bank     = (const float*)d_in[i]; break; // 102,400,000
            case N_BANK:                 metrics      = (const float*)d_in[i]; break; //    50,000
            default: break; // scalar K (=9) ignored, compiled in
        }
    }
    float* out = (float*)d_out;

    // 1) bank inverse norms (both banks): 100000 warps
    {
        int warps = 2 * N_BANK;
        int blocks = (warps * 32 + 255) / 256;
        norm_kernel<<<blocks, 256>>>(sem_bank, dst_bank);
    }

    dim3 gemm_grid((N_BANK + BN - 1) / BN, B_Q / BM);  // (391, 2)

    // 2) semantic branch
    gemm_score_kernel<<<gemm_grid, 256>>>(f_content, sem_bank, /*which=*/0, DIM_S);
    topk_kernel<<<B_Q, 256>>>(metrics, out, /*phase=*/0);

    // 3) distorsion branch (reuses g_scores)
    gemm_score_kernel<<<gemm_grid, 256>>>(f_distorsion, dst_bank, /*which=*/1, DIM_D);
    topk_kernel<<<B_Q, 256>>>(metrics, out, /*phase=*/1);
}

// round 8
// speedup vs baseline: 1.0010x; 1.0010x over previous
#include <cuda_runtime.h>
#include <cstdint>
#include <cstddef>

// Problem constants (fixed by setup_inputs).
#define B_Q    256
#define N_BANK 50000
#define DIM_S  4096
#define DIM_D  2048
#define KTOP   9

// ---------------- static device scratch (no allocations allowed) -------------
__device__ __align__(128) float g_scores[(size_t)B_Q * N_BANK];   // 51.2 MB, reused per branch
__device__ __align__(128) float g_inv_sem[N_BANK];
__device__ __align__(128) float g_inv_dst[N_BANK];
__device__ __align__(128) float g_partial[B_Q];

// ---------------- packed fp32x2 helpers (sm_103a FFMA2 path) -----------------
__device__ __forceinline__ unsigned long long pk2(float lo, float hi) {
    unsigned long long r;
    asm("mov.b64 %0, {%1, %2};" : "=l"(r) : "f"(lo), "f"(hi));
    return r;
}
__device__ __forceinline__ void ffma2(unsigned long long& c,
                                      unsigned long long a,
                                      unsigned long long b) {
    asm("fma.rn.f32x2 %0, %1, %2, %0;" : "+l"(c) : "l"(a), "l"(b));
}
__device__ __forceinline__ float2 upk2(unsigned long long x) {
    float2 f;
    asm("mov.b64 {%0, %1}, %2;" : "=f"(f.x), "=f"(f.y) : "l"(x));
    return f;
}

// ---------------- 1) bank row inverse norms (both banks, one launch) ---------
__global__ void norm_kernel(const float* __restrict__ sem_bank,
                            const float* __restrict__ dst_bank) {
    int gwarp = (blockIdx.x * blockDim.x + threadIdx.x) >> 5;
    int lane  = threadIdx.x & 31;
    const float* bank;
    float* outp;
    int D, row;
    if (gwarp < N_BANK)          { bank = sem_bank; outp = g_inv_sem; D = DIM_S; row = gwarp; }
    else if (gwarp < 2 * N_BANK) { bank = dst_bank; outp = g_inv_dst; D = DIM_D; row = gwarp - N_BANK; }
    else return;

    const float4* r4 = reinterpret_cast<const float4*>(bank + (size_t)row * D);
    float s = 0.f;
    int nv = D >> 2;
    for (int i = lane; i < nv; i += 32) {
        float4 v = r4[i];
        s += v.x * v.x + v.y * v.y + v.z * v.z + v.w * v.w;
    }
    #pragma unroll
    for (int o = 16; o; o >>= 1) s += __shfl_xor_sync(0xffffffffu, s, o);
    if (lane == 0) outp[row] = rsqrtf(s);
}

// ---------------- 2) fp32 GEMM with fused invnorm epilogue -------------------
// C[m, n] = (sum_k A[m,k] * Bank[n,k]) * inv[n],  M=256, N=50000, K in {4096,2048}
// Tile: 128(M) x 128(N) x 8(K), 256 threads, 8x8 per thread (4+4 column split
// so stores are contiguous float4 across a half-warp).
#define BM  128
#define BN  128
#define BKK 8

__global__ __launch_bounds__(256, 2)
void gemm_score_kernel(const float* __restrict__ A,
                       const float* __restrict__ Bank,
                       int which,     // 0 = semantic, 1 = distorsion
                       int K)
{
    __shared__ float As[BKK][BM];
    __shared__ float Bs[BKK][BN];

    const float* __restrict__ inv = which ? g_inv_dst : g_inv_sem;
    float* __restrict__ C = g_scores;

    const int tid = threadIdx.x;
    const int m0  = blockIdx.y * BM;
    const int n0  = blockIdx.x * BN;

    // loader mapping: thread -> (row, k4) inside 128x8 tile, one float4 each
    const int lrow = tid >> 1;
    const int lk   = (tid & 1) << 2;

    // compute mapping: 16x16 thread grid
    const int tm = tid >> 4;   // 0..15 -> rows tm*8 .. tm*8+7
    const int tn = tid & 15;   // 0..15 -> cols tn*4..+3 and 64+tn*4..+3

    const bool brow_ok = (n0 + lrow) < N_BANK;
    const float* Ap = A    + (size_t)(m0 + lrow) * K + lk;
    const float* Bp = Bank + (size_t)(brow_ok ? (n0 + lrow) : 0) * K + lk;

    unsigned long long acc[8][4];
    #pragma unroll
    for (int i = 0; i < 8; i++)
        #pragma unroll
        for (int j = 0; j < 4; j++) acc[i][j] = 0ULL;

    for (int k0 = 0; k0 < K; k0 += BKK) {
        float4 av = *reinterpret_cast<const float4*>(Ap + k0);
        float4 bv = make_float4(0.f, 0.f, 0.f, 0.f);
        if (brow_ok) bv = *reinterpret_cast<const float4*>(Bp + k0);

        As[lk + 0][lrow] = av.x; As[lk + 1][lrow] = av.y;
        As[lk + 2][lrow] = av.z; As[lk + 3][lrow] = av.w;
        Bs[lk + 0][lrow] = bv.x; Bs[lk + 1][lrow] = bv.y;
        Bs[lk + 2][lrow] = bv.z; Bs[lk + 3][lrow] = bv.w;
        __syncthreads();

        #pragma unroll
        for (int kk = 0; kk < BKK; kk++) {
            float4 a0 = *reinterpret_cast<const float4*>(&As[kk][tm * 8]);
            float4 a1 = *reinterpret_cast<const float4*>(&As[kk][tm * 8 + 4]);
            float4 b0 = *reinterpret_cast<const float4*>(&Bs[kk][tn * 4]);
            float4 b1 = *reinterpret_cast<const float4*>(&Bs[kk][64 + tn * 4]);

            unsigned long long bp0 = pk2(b0.x, b0.y);
            unsigned long long bp1 = pk2(b0.z, b0.w);
            unsigned long long bp2 = pk2(b1.x, b1.y);
            unsigned long long bp3 = pk2(b1.z, b1.w);
            float a[8] = {a0.x, a0.y, a0.z, a0.w, a1.x, a1.y, a1.z, a1.w};

            #pragma unroll
            for (int i = 0; i < 8; i++) {
                unsigned long long ad = pk2(a[i], a[i]);
                ffma2(acc[i][0], ad, bp0);
                ffma2(acc[i][1], ad, bp1);
                ffma2(acc[i][2], ad, bp2);
                ffma2(acc[i][3], ad, bp3);
            }
        }
        __syncthreads();
    }

    // epilogue: scale by bank inverse norm, store scores
    const int c0 = n0 + tn * 4;
    const int c1 = n0 + 64 + tn * 4;
    float w0[4], w1[4];
    #pragma unroll
    for (int j = 0; j < 4; j++) {
        w0[j] = (c0 + j < N_BANK) ? inv[c0 + j] : 0.f;
        w1[j] = (c1 + j < N_BANK) ? inv[c1 + j] : 0.f;
    }
    #pragma unroll
    for (int i = 0; i < 8; i++) {
        const int r = m0 + tm * 8 + i;
        float* cp = C + (size_t)r * N_BANK;
        float2 p0 = upk2(acc[i][0]); float2 p1 = upk2(acc[i][1]);
        float2 p2 = upk2(acc[i][2]); float2 p3 = upk2(acc[i][3]);
        float o0[4] = { p0.x * w0[0], p0.y * w0[1], p1.x * w0[2], p1.y * w0[3] };
        float o1[4] = { p2.x * w1[0], p2.y * w1[1], p3.x * w1[2], p3.y * w1[3] };
        if (c0 + 3 < N_BANK) {
            *reinterpret_cast<float4*>(cp + c0) = make_float4(o0[0], o0[1], o0[2], o0[3]);
        } else {
            #pragma unroll
            for (int j = 0; j < 4; j++) if (c0 + j < N_BANK) cp[c0 + j] = o0[j];
        }
        if (c1 + 3 < N_BANK) {
            *reinterpret_cast<float4*>(cp + c1) = make_float4(o1[0], o1[1], o1[2], o1[3]);
        } else {
            #pragma unroll
            for (int j = 0; j < 4; j++) if (c1 + j < N_BANK) cp[c1 + j] = o1[j];
        }
    }
}

// ---------------- 3) top-9 per row + metrics gather --------------------------
__device__ __forceinline__ void ins9(float s, int n, float v[KTOP], int id[KTOP]) {
    if (s <= v[KTOP - 1]) return;
    v[KTOP - 1]  = s;
    id[KTOP - 1] = n;
    #pragma unroll
    for (int q = KTOP - 1; q > 0; q--) {
        if (v[q] > v[q - 1]) {
            float tv = v[q]; v[q] = v[q - 1]; v[q - 1] = tv;
            int   ti = id[q]; id[q] = id[q - 1]; id[q - 1] = ti;
        }
    }
}

__global__ void topk_kernel(const float* __restrict__ metrics,
                            float* __restrict__ out,
                            int phase)   // 0: write g_partial; 1: finalize out
{
    __shared__ float sv[256 * KTOP];
    __shared__ int   si[256 * KTOP];
    __shared__ float sv2[32 * KTOP];
    __shared__ int   si2[32 * KTOP];

    const int b   = blockIdx.x;
    const int tid = threadIdx.x;
    const float* row = g_scores + (size_t)b * N_BANK;

    float v[KTOP]; int id[KTOP];
    #pragma unroll
    for (int i = 0; i < KTOP; i++) { v[i] = -3.402823466e38f; id[i] = 0; }

    for (int n = tid; n < N_BANK; n += 256) ins9(row[n], n, v, id);

    #pragma unroll
    for (int i = 0; i < KTOP; i++) { sv[tid * KTOP + i] = v[i]; si[tid * KTOP + i] = id[i]; }
    __syncthreads();

    if (tid < 32) {
        float mv[KTOP]; int mi[KTOP];
        #pragma unroll
        for (int i = 0; i < KTOP; i++) { mv[i] = -3.402823466e38f; mi[i] = 0; }
        for (int t = tid * 8; t < tid * 8 + 8; t++)
            for (int i = 0; i < KTOP; i++)
                ins9(sv[t * KTOP + i], si[t * KTOP + i], mv, mi);
        #pragma unroll
        for (int i = 0; i < KTOP; i++) { sv2[tid * KTOP + i] = mv[i]; si2[tid * KTOP + i] = mi[i]; }
    }
    __syncthreads();

    if (tid == 0) {
        float mv[KTOP]; int mi[KTOP];
        #pragma unroll
        for (int i = 0; i < KTOP; i++) { mv[i] = -3.402823466e38f; mi[i] = 0; }
        for (int t = 0; t < 32; t++)
            for (int i = 0; i < KTOP; i++)
                ins9(sv2[t * KTOP + i], si2[t * KTOP + i], mv, mi);
        float ssum = 0.f;
        #pragma unroll
        for (int i = 0; i < KTOP; i++) ssum += metrics[mi[i]];
        if (phase == 0) g_partial[b] = ssum;
        else            out[b] = (g_partial[b] + ssum) * (1.f / (2.f * KTOP));
    }
}

// ---------------- launch ------------------------------------------------------
extern "C" void kernel_launch(void* const* d_in, const int* in_sizes, int n_in,
                              void* d_out, int out_size) {
    // Identify inputs by element count (all distinct), robust to metadata order.
    const float* f_content    = nullptr;
    const float* f_distorsion = nullptr;
    const float* sem_bank     = nullptr;
    const float* dst_bank     = nullptr;
    const float* metrics      = nullptr;
    for (int i = 0; i < n_in; i++) {
        switch (in_sizes[i]) {
            case B_Q * DIM_S:            f_content    = (const float*)d_in[i]; break; // 1,048,576
            case B_Q * DIM_D:            f_distorsion = (const float*)d_in[i]; break; //   524,288
            case N_BANK * DIM_S:         sem_bank     = (const float*)d_in[i]; break; // 204,800,000
            case N_BANK * DIM_D:         dst_bank     = (const float*)d_in[i]; break; // 102,400,000
            case N_BANK:                 metrics      = (const float*)d_in[i]; break; //    50,000
            default: break; // scalar K (=9) ignored, compiled in
        }
    }
    float* out = (float*)d_out;

    // 1) bank inverse norms (both banks): 100000 warps
    {
        int warps = 2 * N_BANK;
        int blocks = (warps * 32 + 255) / 256;
        norm_kernel<<<blocks, 256>>>(sem_bank, dst_bank);
    }

    dim3 gemm_grid((N_BANK + BN - 1) / BN, B_Q / BM);  // (391, 2)

    // 2) semantic branch
    gemm_score_kernel<<<gemm_grid, 256>>>(f_content, sem_bank, /*which=*/0, DIM_S);
    topk_kernel<<<B_Q, 256>>>(metrics, out, /*phase=*/0);

    // 3) distorsion branch (reuses g_scores)
    gemm_score_kernel<<<gemm_grid, 256>>>(f_distorsion, dst_bank, /*which=*/1, DIM_D);
    topk_kernel<<<B_Q, 256>>>(metrics, out, /*phase=*/1);
}

// round 10
// speedup vs baseline: 1.9831x; 1.9811x over previous
#include <cuda_runtime.h>
#include <cuda_bf16.h>
#include <cstdint>
#include <cstddef>

// Problem constants (fixed by setup_inputs).
#define B_Q    256
#define N_BANK 50000
#define DIM_S  4096
#define DIM_D  2048
#define KTOP   9

// GEMM tiling
#define TILE_M   128
#define TILE_N   128
#define CH       32                 // fp32 K per chunk
#define T_STRIDE 80                 // bytes per bf16 tile row (64B data + 16B pad)
#define T_SIZE   (128 * T_STRIDE)   // 10240 bytes per tile
#define STAGE    (4 * T_SIZE)       // Ah, Al, Bh, Bl
#define OFF_INV  (2 * STAGE)        // 81920
#define SMEM_TOTAL (OFF_INV + 512)

// ---------------- static device scratch (no allocations allowed) -------------
__device__ __align__(128) float g_scores[(size_t)B_Q * N_BANK];   // 51.2 MB
__device__ __align__(128) float g_partial[B_Q];

// ---------------- PTX helpers -------------------------------------------------
__device__ __forceinline__ uint32_t smem_u32(const void* p) {
    uint32_t a;
    asm("{ .reg .u64 t; cvta.to.shared.u64 t, %1; cvt.u32.u64 %0, t; }" : "=r"(a) : "l"(p));
    return a;
}
__device__ __forceinline__ void sts64(uint32_t addr, uint32_t a, uint32_t b) {
    asm volatile("st.shared.v2.b32 [%0], {%1,%2};" :: "r"(addr), "r"(a), "r"(b));
}
#define LDSM4(r, addr) \
    asm volatile("ldmatrix.sync.aligned.m8n8.x4.shared.b16 {%0,%1,%2,%3}, [%4];" \
        : "=r"((r)[0]), "=r"((r)[1]), "=r"((r)[2]), "=r"((r)[3]) : "r"(addr))

#define MMA16816(d, a, b0, b1) \
    asm volatile("mma.sync.aligned.m16n8k16.row.col.f32.bf16.bf16.f32 " \
        "{%0,%1,%2,%3}, {%4,%5,%6,%7}, {%8,%9}, {%0,%1,%2,%3};" \
        : "+f"((d)[0]), "+f"((d)[1]), "+f"((d)[2]), "+f"((d)[3]) \
        : "r"((a)[0]), "r"((a)[1]), "r"((a)[2]), "r"((a)[3]), "r"(b0), "r"(b1))

// convert float4 -> packed bf16 hi pair/lo pair (low 16 bits = lower column)
__device__ __forceinline__ void cvt_f4(float4 v, uint32_t& h0, uint32_t& h1,
                                       uint32_t& l0, uint32_t& l1) {
    asm("cvt.rn.bf16x2.f32 %0, %1, %2;" : "=r"(h0) : "f"(v.y), "f"(v.x));
    asm("cvt.rn.bf16x2.f32 %0, %1, %2;" : "=r"(h1) : "f"(v.w), "f"(v.z));
    float hx = __uint_as_float(h0 << 16);
    float hy = __uint_as_float(h0 & 0xFFFF0000u);
    float hz = __uint_as_float(h1 << 16);
    float hw = __uint_as_float(h1 & 0xFFFF0000u);
    asm("cvt.rn.bf16x2.f32 %0, %1, %2;" : "=r"(l0) : "f"(v.y - hy), "f"(v.x - hx));
    asm("cvt.rn.bf16x2.f32 %0, %1, %2;" : "=r"(l1) : "f"(v.w - hw), "f"(v.z - hz));
}

// ---------------- HMMA GEMM: scores = (A . B^T) * rsqrt(rowsum(B^2)) ----------
// grid (2, ceil(N/128)), block 256.  A[M,K] row-major, Bank[N,K] row-major.
__global__ __launch_bounds__(256, 1)
void gemm_hmma_kernel(const float* __restrict__ A,
                      const float* __restrict__ Bank,
                      int K)
{
    extern __shared__ char smem[];
    const uint32_t sb = smem_u32(smem);
    const int tid = threadIdx.x;
    const int w = tid >> 5, l = tid & 31;
    const int wm = w >> 2, wn = w & 3;           // warp grid 2 x 4
    const int m0 = blockIdx.x * TILE_M;
    const int n0 = blockIdx.y * TILE_N;
    const int NC = K >> 5;

    // ---- loader mapping: 2 threads per row, 16 fp32 cols each (4 float4) ----
    const int lrow  = tid >> 1;                  // 0..127
    const int lcolf = (tid & 1) << 4;            // 0 or 16 (fp32 index)
    const float* Ap = A + (size_t)(m0 + lrow) * K + lcolf;
    const bool  bok = (n0 + lrow) < N_BANK;
    const float* Bp = Bank + (size_t)(bok ? (n0 + lrow) : 0) * K + lcolf;
    const uint32_t sts_off = (uint32_t)(lrow * T_STRIDE + lcolf * 2);

    // ---- ldmatrix lane offsets ----
    // A: lanes 0-15 -> rows, lanes 16-31 -> rows with +16B column half
    const uint32_t a_loff = (uint32_t)((wm * 64 + (l & 15)) * T_STRIDE + (l >> 4) * 16);
    // B: all 32 lanes are n-rows (4 x 8-row groups -> ni = 0..3)
    const uint32_t b_loff = (uint32_t)((wn * 32 + l) * T_STRIDE);

    float acc[4][4][4];
    #pragma unroll
    for (int i = 0; i < 4; i++)
        #pragma unroll
        for (int j = 0; j < 4; j++)
            #pragma unroll
            for (int e = 0; e < 4; e++) acc[i][j][e] = 0.f;

    float bsum = 0.f;

    // ---- prologue: load chunk 0, convert, STS stage 0 ----
    {
        float4 av[4], bv[4];
        #pragma unroll
        for (int j = 0; j < 4; j++)
            av[j] = *reinterpret_cast<const float4*>(Ap + 4 * j);
        #pragma unroll
        for (int j = 0; j < 4; j++)
            bv[j] = bok ? *reinterpret_cast<const float4*>(Bp + 4 * j)
                        : make_float4(0.f, 0.f, 0.f, 0.f);
        #pragma unroll
        for (int j = 0; j < 4; j++)
            bsum += bv[j].x * bv[j].x + bv[j].y * bv[j].y +
                    bv[j].z * bv[j].z + bv[j].w * bv[j].w;
        uint32_t st = sb;
        #pragma unroll
        for (int j = 0; j < 4; j++) {
            uint32_t h0, h1, l0, l1;
            cvt_f4(av[j], h0, h1, l0, l1);
            sts64(st + sts_off + 8 * j, h0, h1);
            sts64(st + T_SIZE + sts_off + 8 * j, l0, l1);
            cvt_f4(bv[j], h0, h1, l0, l1);
            sts64(st + 2 * T_SIZE + sts_off + 8 * j, h0, h1);
            sts64(st + 3 * T_SIZE + sts_off + 8 * j, l0, l1);
        }
    }
    __syncthreads();

    // ---- main loop ----
    #pragma unroll 1
    for (int ch = 0; ch < NC; ch++) {
        const int cur = ch & 1;
        const uint32_t base = sb + (uint32_t)cur * STAGE;

        // prefetch next chunk (global loads overlap the MMA block below)
        float4 av[4], bv[4];
        const bool pf = (ch + 1 < NC);
        if (pf) {
            const int k0 = (ch + 1) << 5;
            #pragma unroll
            for (int j = 0; j < 4; j++)
                av[j] = *reinterpret_cast<const float4*>(Ap + k0 + 4 * j);
            #pragma unroll
            for (int j = 0; j < 4; j++)
                bv[j] = bok ? *reinterpret_cast<const float4*>(Bp + k0 + 4 * j)
                            : make_float4(0.f, 0.f, 0.f, 0.f);
        }

        // MMA on stage `cur`: 2 k16-steps x (AhBh + AhBl + AlBh)
        #pragma unroll
        for (int kc = 0; kc < 2; kc++) {
            const uint32_t kb = (uint32_t)kc * 32;
            uint32_t ah[4][4], alr[4][4], bh[2][4], bl[2][4];
            #pragma unroll
            for (int mi = 0; mi < 4; mi++)
                LDSM4(ah[mi], base + a_loff + (uint32_t)mi * (16 * T_STRIDE) + kb);
            #pragma unroll
            for (int mi = 0; mi < 4; mi++)
                LDSM4(alr[mi], base + T_SIZE + a_loff + (uint32_t)mi * (16 * T_STRIDE) + kb);
            LDSM4(bh[0], base + 2 * T_SIZE + b_loff + kb);
            LDSM4(bh[1], base + 2 * T_SIZE + b_loff + kb + 16);
            LDSM4(bl[0], base + 3 * T_SIZE + b_loff + kb);
            LDSM4(bl[1], base + 3 * T_SIZE + b_loff + kb + 16);

            #pragma unroll
            for (int mi = 0; mi < 4; mi++)
                #pragma unroll
                for (int ni = 0; ni < 4; ni++) {
                    MMA16816(acc[mi][ni], ah[mi],  bh[0][ni], bh[1][ni]);
                    MMA16816(acc[mi][ni], ah[mi],  bl[0][ni], bl[1][ni]);
                    MMA16816(acc[mi][ni], alr[mi], bh[0][ni], bh[1][ni]);
                }
        }

        // convert + STS next chunk into the other stage
        if (pf) {
            #pragma unroll
            for (int j = 0; j < 4; j++)
                bsum += bv[j].x * bv[j].x + bv[j].y * bv[j].y +
                        bv[j].z * bv[j].z + bv[j].w * bv[j].w;
            const uint32_t st = sb + (uint32_t)(cur ^ 1) * STAGE;
            #pragma unroll
            for (int j = 0; j < 4; j++) {
                uint32_t h0, h1, l0, l1;
                cvt_f4(av[j], h0, h1, l0, l1);
                sts64(st + sts_off + 8 * j, h0, h1);
                sts64(st + T_SIZE + sts_off + 8 * j, l0, l1);
                cvt_f4(bv[j], h0, h1, l0, l1);
                sts64(st + 2 * T_SIZE + sts_off + 8 * j, h0, h1);
                sts64(st + 3 * T_SIZE + sts_off + 8 * j, l0, l1);
            }
        }
        __syncthreads();
    }

    // ---- per-row inverse norms (row owned by thread pair (2r, 2r+1)) ----
    float* s_inv = reinterpret_cast<float*>(smem + OFF_INV);
    {
        float v = bsum + __shfl_xor_sync(0xffffffffu, bsum, 1);
        if ((tid & 1) == 0)
            s_inv[lrow] = (v > 0.f) ? rsqrtf(v) : 0.f;
    }
    __syncthreads();

    // ---- epilogue: scale + store scores ----
    {
        const int qr = l >> 2;              // 0..7
        const int qc = (l & 3) * 2;         // 0,2,4,6
        #pragma unroll
        for (int mi = 0; mi < 4; mi++) {
            const int m = m0 + wm * 64 + mi * 16 + qr;
            float* crow0 = g_scores + (size_t)m * N_BANK;
            float* crow1 = crow0 + (size_t)8 * N_BANK;
            #pragma unroll
            for (int ni = 0; ni < 4; ni++) {
                const int nloc = wn * 32 + ni * 8 + qc;
                const int ng = n0 + nloc;
                const float i0 = s_inv[nloc], i1 = s_inv[nloc + 1];
                const float* d = acc[mi][ni];
                if (ng + 1 < N_BANK) {
                    *reinterpret_cast<float2*>(crow0 + ng) =
                        make_float2(d[0] * i0, d[1] * i1);
                    *reinterpret_cast<float2*>(crow1 + ng) =
                        make_float2(d[2] * i0, d[3] * i1);
                } else if (ng < N_BANK) {
                    crow0[ng] = d[0] * i0;
                    crow1[ng] = d[2] * i0;
                }
            }
        }
    }
}

// ---------------- top-9 per row + metrics gather ------------------------------
__device__ __forceinline__ void ins9(float s, int n, float v[KTOP], int id[KTOP]) {
    if (s <= v[KTOP - 1]) return;
    v[KTOP - 1]  = s;
    id[KTOP - 1] = n;
    #pragma unroll
    for (int q = KTOP - 1; q > 0; q--) {
        if (v[q] > v[q - 1]) {
            float tv = v[q]; v[q] = v[q - 1]; v[q - 1] = tv;
            int   ti = id[q]; id[q] = id[q - 1]; id[q - 1] = ti;
        }
    }
}

__global__ void topk_kernel(const float* __restrict__ metrics,
                            float* __restrict__ out,
                            int phase)   // 0: write g_partial; 1: finalize out
{
    __shared__ float sv[256 * KTOP];
    __shared__ int   si[256 * KTOP];
    __shared__ float sv2[32 * KTOP];
    __shared__ int   si2[32 * KTOP];

    const int b   = blockIdx.x;
    const int tid = threadIdx.x;
    const float* row = g_scores + (size_t)b * N_BANK;

    float v[KTOP]; int id[KTOP];
    #pragma unroll
    for (int i = 0; i < KTOP; i++) { v[i] = -3.402823466e38f; id[i] = 0; }

    for (int n = tid; n < N_BANK; n += 256) ins9(row[n], n, v, id);

    #pragma unroll
    for (int i = 0; i < KTOP; i++) { sv[tid * KTOP + i] = v[i]; si[tid * KTOP + i] = id[i]; }
    __syncthreads();

    if (tid < 32) {
        float mv[KTOP]; int mi[KTOP];
        #pragma unroll
        for (int i = 0; i < KTOP; i++) { mv[i] = -3.402823466e38f; mi[i] = 0; }
        for (int t = tid * 8; t < tid * 8 + 8; t++)
            for (int i = 0; i < KTOP; i++)
                ins9(sv[t * KTOP + i], si[t * KTOP + i], mv, mi);
        #pragma unroll
        for (int i = 0; i < KTOP; i++) { sv2[tid * KTOP + i] = mv[i]; si2[tid * KTOP + i] = mi[i]; }
    }
    __syncthreads();

    if (tid == 0) {
        float mv[KTOP]; int mi[KTOP];
        #pragma unroll
        for (int i = 0; i < KTOP; i++) { mv[i] = -3.402823466e38f; mi[i] = 0; }
        for (int t = 0; t < 32; t++)
            for (int i = 0; i < KTOP; i++)
                ins9(sv2[t * KTOP + i], si2[t * KTOP + i], mv, mi);
        float ssum = 0.f;
        #pragma unroll
        for (int i = 0; i < KTOP; i++) ssum += metrics[mi[i]];
        if (phase == 0) g_partial[b] = ssum;
        else            out[b] = (g_partial[b] + ssum) * (1.f / (2.f * KTOP));
    }
}

// ---------------- launch ------------------------------------------------------
extern "C" void kernel_launch(void* const* d_in, const int* in_sizes, int n_in,
                              void* d_out, int out_size) {
    const float* f_content    = nullptr;
    const float* f_distorsion = nullptr;
    const float* sem_bank     = nullptr;
    const float* dst_bank     = nullptr;
    const float* metrics      = nullptr;
    for (int i = 0; i < n_in; i++) {
        switch (in_sizes[i]) {
            case B_Q * DIM_S:    f_content    = (const float*)d_in[i]; break;
            case B_Q * DIM_D:    f_distorsion = (const float*)d_in[i]; break;
            case N_BANK * DIM_S: sem_bank     = (const float*)d_in[i]; break;
            case N_BANK * DIM_D: dst_bank     = (const float*)d_in[i]; break;
            case N_BANK:         metrics      = (const float*)d_in[i]; break;
            default: break; // scalar K (=9) compiled in
        }
    }
    float* out = (float*)d_out;

    cudaFuncSetAttribute(gemm_hmma_kernel,
                         cudaFuncAttributeMaxDynamicSharedMemorySize, SMEM_TOTAL);

    // m-index fastest so the 2 CTAs sharing a B stripe are L2-co-resident
    dim3 grid(B_Q / TILE_M, (N_BANK + TILE_N - 1) / TILE_N);   // (2, 391)

    // semantic branch (bank norms fused into GEMM)
    gemm_hmma_kernel<<<grid, 256, SMEM_TOTAL>>>(f_content, sem_bank, DIM_S);
    topk_kernel<<<B_Q, 256>>>(metrics, out, /*phase=*/0);

    // distorsion branch (reuses g_scores)
    gemm_hmma_kernel<<<grid, 256, SMEM_TOTAL>>>(f_distorsion, dst_bank, DIM_D);
    topk_kernel<<<B_Q, 256>>>(metrics, out, /*phase=*/1);
}

// round 11
// speedup vs baseline: 3.4131x; 1.7211x over previous
#include <cuda_runtime.h>
#include <cuda_bf16.h>
#include <cstdint>
#include <cstddef>

// Problem constants (fixed by setup_inputs).
#define B_Q    256
#define N_BANK 50000
#define DIM_S  4096
#define DIM_D  2048
#define KTOP   9

// GEMM tiling
#define TILE_M   128
#define TILE_N   128
#define T_STRIDE 80                 // bytes per bf16 tile row (64B data + 16B pad)
#define T_SIZE   (128 * T_STRIDE)   // 10240 bytes per tile
#define STAGE    (2 * T_SIZE)       // Ah, Bh only (1-pass bf16)
#define OFF_INV  (2 * STAGE)        // 40960
#define SMEM_TOTAL (OFF_INV + 512)

// Candidate selection
#define NSEG    2
#define SEG_LEN (N_BANK / NSEG)     // 25000
#define CPS     12                  // candidates per segment
#define NCAND   (NSEG * CPS)        // 24 per row

// ---------------- static device scratch (no allocations allowed) -------------
__device__ __align__(128) float g_scores[(size_t)B_Q * N_BANK];   // 51.2 MB
__device__ __align__(128) float g_partial[B_Q];
__device__ __align__(128) int   g_cand[B_Q * NCAND];

// ---------------- PTX helpers -------------------------------------------------
__device__ __forceinline__ uint32_t smem_u32(const void* p) {
    uint32_t a;
    asm("{ .reg .u64 t; cvta.to.shared.u64 t, %1; cvt.u32.u64 %0, t; }" : "=r"(a) : "l"(p));
    return a;
}
__device__ __forceinline__ void sts64(uint32_t addr, uint32_t a, uint32_t b) {
    asm volatile("st.shared.v2.b32 [%0], {%1,%2};" :: "r"(addr), "r"(a), "r"(b));
}
#define LDSM4(r, addr) \
    asm volatile("ldmatrix.sync.aligned.m8n8.x4.shared.b16 {%0,%1,%2,%3}, [%4];" \
        : "=r"((r)[0]), "=r"((r)[1]), "=r"((r)[2]), "=r"((r)[3]) : "r"(addr))

#define MMA16816(d, a, b0, b1) \
    asm volatile("mma.sync.aligned.m16n8k16.row.col.f32.bf16.bf16.f32 " \
        "{%0,%1,%2,%3}, {%4,%5,%6,%7}, {%8,%9}, {%0,%1,%2,%3};" \
        : "+f"((d)[0]), "+f"((d)[1]), "+f"((d)[2]), "+f"((d)[3]) \
        : "r"((a)[0]), "r"((a)[1]), "r"((a)[2]), "r"((a)[3]), "r"(b0), "r"(b1))

// float4 -> two packed bf16x2 (low 16 bits = lower column)
__device__ __forceinline__ void cvt_hi(float4 v, uint32_t& h0, uint32_t& h1) {
    asm("cvt.rn.bf16x2.f32 %0, %1, %2;" : "=r"(h0) : "f"(v.y), "f"(v.x));
    asm("cvt.rn.bf16x2.f32 %0, %1, %2;" : "=r"(h1) : "f"(v.w), "f"(v.z));
}

// ---------------- 1) 1-pass bf16 HMMA GEMM (+ fused invnorm) ------------------
// scores[m,n] = bf16(A[m,:]) . bf16(Bank[n,:]) * rsqrt(sum(Bank[n,:]^2))
__global__ __launch_bounds__(256, 2)
void gemm_hmma_kernel(const float* __restrict__ A,
                      const float* __restrict__ Bank,
                      int K)
{
    extern __shared__ char smem[];
    const uint32_t sb = smem_u32(smem);
    const int tid = threadIdx.x;
    const int w = tid >> 5, l = tid & 31;
    const int wm = w >> 2, wn = w & 3;           // warp grid 2 x 4
    const int m0 = blockIdx.x * TILE_M;
    const int n0 = blockIdx.y * TILE_N;
    const int NC = K >> 5;

    // loader mapping: 2 threads per row, 16 fp32 cols each (4 float4)
    const int lrow  = tid >> 1;                  // 0..127
    const int lcolf = (tid & 1) << 4;            // 0 or 16 (fp32 index)
    const float* Ap = A + (size_t)(m0 + lrow) * K + lcolf;
    const bool  bok = (n0 + lrow) < N_BANK;
    const float* Bp = Bank + (size_t)(bok ? (n0 + lrow) : 0) * K + lcolf;
    const uint32_t sts_off = (uint32_t)(lrow * T_STRIDE + lcolf * 2);

    // ldmatrix lane offsets
    const uint32_t a_loff = (uint32_t)((wm * 64 + (l & 15)) * T_STRIDE + (l >> 4) * 16);
    const uint32_t b_loff = (uint32_t)((wn * 32 + l) * T_STRIDE);

    float acc[4][4][4];
    #pragma unroll
    for (int i = 0; i < 4; i++)
        #pragma unroll
        for (int j = 0; j < 4; j++)
            #pragma unroll
            for (int e = 0; e < 4; e++) acc[i][j][e] = 0.f;

    float bsum = 0.f;

    // prologue: chunk 0 -> stage 0
    {
        float4 av[4], bv[4];
        #pragma unroll
        for (int j = 0; j < 4; j++)
            av[j] = *reinterpret_cast<const float4*>(Ap + 4 * j);
        #pragma unroll
        for (int j = 0; j < 4; j++)
            bv[j] = bok ? *reinterpret_cast<const float4*>(Bp + 4 * j)
                        : make_float4(0.f, 0.f, 0.f, 0.f);
        #pragma unroll
        for (int j = 0; j < 4; j++)
            bsum += bv[j].x * bv[j].x + bv[j].y * bv[j].y +
                    bv[j].z * bv[j].z + bv[j].w * bv[j].w;
        #pragma unroll
        for (int j = 0; j < 4; j++) {
            uint32_t h0, h1;
            cvt_hi(av[j], h0, h1); sts64(sb + sts_off + 8 * j, h0, h1);
            cvt_hi(bv[j], h0, h1); sts64(sb + T_SIZE + sts_off + 8 * j, h0, h1);
        }
    }
    __syncthreads();

    #pragma unroll 1
    for (int ch = 0; ch < NC; ch++) {
        const int cur = ch & 1;
        const uint32_t base = sb + (uint32_t)cur * STAGE;

        float4 av[4], bv[4];
        const bool pf = (ch + 1 < NC);
        if (pf) {
            const int k0 = (ch + 1) << 5;
            #pragma unroll
            for (int j = 0; j < 4; j++)
                av[j] = *reinterpret_cast<const float4*>(Ap + k0 + 4 * j);
            #pragma unroll
            for (int j = 0; j < 4; j++)
                bv[j] = bok ? *reinterpret_cast<const float4*>(Bp + k0 + 4 * j)
                            : make_float4(0.f, 0.f, 0.f, 0.f);
        }

        // MMA on stage `cur`: 2 k16-steps, hi*hi only
        #pragma unroll
        for (int kc = 0; kc < 2; kc++) {
            const uint32_t kb = (uint32_t)kc * 32;
            uint32_t ah[4][4], bh[2][4];
            #pragma unroll
            for (int mi = 0; mi < 4; mi++)
                LDSM4(ah[mi], base + a_loff + (uint32_t)mi * (16 * T_STRIDE) + kb);
            LDSM4(bh[0], base + T_SIZE + b_loff + kb);
            LDSM4(bh[1], base + T_SIZE + b_loff + kb + 16);

            #pragma unroll
            for (int mi = 0; mi < 4; mi++)
                #pragma unroll
                for (int ni = 0; ni < 4; ni++)
                    MMA16816(acc[mi][ni], ah[mi], bh[0][ni], bh[1][ni]);
        }

        if (pf) {
            #pragma unroll
            for (int j = 0; j < 4; j++)
                bsum += bv[j].x * bv[j].x + bv[j].y * bv[j].y +
                        bv[j].z * bv[j].z + bv[j].w * bv[j].w;
            const uint32_t st = sb + (uint32_t)(cur ^ 1) * STAGE;
            #pragma unroll
            for (int j = 0; j < 4; j++) {
                uint32_t h0, h1;
                cvt_hi(av[j], h0, h1); sts64(st + sts_off + 8 * j, h0, h1);
                cvt_hi(bv[j], h0, h1); sts64(st + T_SIZE + sts_off + 8 * j, h0, h1);
            }
        }
        __syncthreads();
    }

    // per-row inverse norms (row owned by thread pair (2r, 2r+1))
    float* s_inv = reinterpret_cast<float*>(smem + OFF_INV);
    {
        float v = bsum + __shfl_xor_sync(0xffffffffu, bsum, 1);
        if ((tid & 1) == 0)
            s_inv[lrow] = (v > 0.f) ? rsqrtf(v) : 0.f;
    }
    __syncthreads();

    // epilogue: scale + store approx scores
    {
        const int qr = l >> 2;
        const int qc = (l & 3) * 2;
        #pragma unroll
        for (int mi = 0; mi < 4; mi++) {
            const int m = m0 + wm * 64 + mi * 16 + qr;
            float* crow0 = g_scores + (size_t)m * N_BANK;
            float* crow1 = crow0 + (size_t)8 * N_BANK;
            #pragma unroll
            for (int ni = 0; ni < 4; ni++) {
                const int nloc = wn * 32 + ni * 8 + qc;
                const int ng = n0 + nloc;
                const float i0 = s_inv[nloc], i1 = s_inv[nloc + 1];
                const float* d = acc[mi][ni];
                if (ng + 1 < N_BANK) {
                    *reinterpret_cast<float2*>(crow0 + ng) =
                        make_float2(d[0] * i0, d[1] * i1);
                    *reinterpret_cast<float2*>(crow1 + ng) =
                        make_float2(d[2] * i0, d[3] * i1);
                } else if (ng < N_BANK) {
                    crow0[ng] = d[0] * i0;
                    crow1[ng] = d[2] * i0;
                }
            }
        }
    }
}

// ---------------- 2) candidate selection: top-12 per half-row -----------------
__device__ __forceinline__ void ins_n(float s, int n, float* v, int* id, int depth) {
    if (s <= v[depth - 1]) return;
    v[depth - 1]  = s;
    id[depth - 1] = n;
    for (int q = depth - 1; q > 0; q--) {
        if (v[q] > v[q - 1]) {
            float tv = v[q]; v[q] = v[q - 1]; v[q - 1] = tv;
            int   ti = id[q]; id[q] = id[q - 1]; id[q - 1] = ti;
        } else break;
    }
}

__global__ void select_kernel() {
    __shared__ float sv[256 * 4];
    __shared__ int   si[256 * 4];
    __shared__ float sv2[32 * CPS];
    __shared__ int   si2[32 * CPS];

    const int row = blockIdx.x, seg = blockIdx.y, tid = threadIdx.x;
    const float4* p = reinterpret_cast<const float4*>(
        g_scores + (size_t)row * N_BANK + seg * SEG_LEN);
    const int nv = SEG_LEN / 4;              // 6250

    float v[4]; int id[4];
    #pragma unroll
    for (int i = 0; i < 4; i++) { v[i] = -3.402823466e38f; id[i] = 0; }

    for (int i = tid; i < nv; i += 256) {
        float4 x = p[i];
        const int base = seg * SEG_LEN + i * 4;
        ins_n(x.x, base + 0, v, id, 4);
        ins_n(x.y, base + 1, v, id, 4);
        ins_n(x.z, base + 2, v, id, 4);
        ins_n(x.w, base + 3, v, id, 4);
    }
    #pragma unroll
    for (int i = 0; i < 4; i++) { sv[tid * 4 + i] = v[i]; si[tid * 4 + i] = id[i]; }
    __syncthreads();

    if (tid < 32) {
        float mv[CPS]; int mi[CPS];
        #pragma unroll
        for (int i = 0; i < CPS; i++) { mv[i] = -3.402823466e38f; mi[i] = 0; }
        for (int t = tid * 8; t < tid * 8 + 8; t++)
            #pragma unroll
            for (int i = 0; i < 4; i++)
                ins_n(sv[t * 4 + i], si[t * 4 + i], mv, mi, CPS);
        #pragma unroll
        for (int i = 0; i < CPS; i++) { sv2[tid * CPS + i] = mv[i]; si2[tid * CPS + i] = mi[i]; }
    }
    __syncthreads();

    if (tid == 0) {
        float mv[CPS]; int mi[CPS];
        #pragma unroll
        for (int i = 0; i < CPS; i++) { mv[i] = -3.402823466e38f; mi[i] = 0; }
        for (int t = 0; t < 32; t++)
            #pragma unroll
            for (int i = 0; i < CPS; i++)
                ins_n(sv2[t * CPS + i], si2[t * CPS + i], mv, mi, CPS);
        #pragma unroll
        for (int i = 0; i < CPS; i++)
            g_cand[row * NCAND + seg * CPS + i] = mi[i];
    }
}

// ---------------- 3) exact fp32 rescore + top-9 + metrics mean ----------------
__global__ void rescore_kernel(const float* __restrict__ A,
                               const float* __restrict__ Bank,
                               int K,
                               const float* __restrict__ metrics,
                               float* __restrict__ out,
                               int phase)
{
    __shared__ float ss[NCAND];
    const int row = blockIdx.x;
    const int w = threadIdx.x >> 5, l = threadIdx.x & 31;
    const float4* q4 = reinterpret_cast<const float4*>(A + (size_t)row * K);
    const int kv = K >> 2;

    for (int c = w; c < NCAND; c += 8) {
        const int idx = g_cand[row * NCAND + c];
        const float4* b4 = reinterpret_cast<const float4*>(Bank + (size_t)idx * K);
        float dot = 0.f, bsq = 0.f;
        for (int i = l; i < kv; i += 32) {
            float4 b = b4[i], q = q4[i];
            dot += q.x * b.x + q.y * b.y + q.z * b.z + q.w * b.w;
            bsq += b.x * b.x + b.y * b.y + b.z * b.z + b.w * b.w;
        }
        #pragma unroll
        for (int o = 16; o; o >>= 1) {
            dot += __shfl_xor_sync(0xffffffffu, dot, o);
            bsq += __shfl_xor_sync(0xffffffffu, bsq, o);
        }
        if (l == 0) ss[c] = dot * rsqrtf(bsq);
    }
    __syncthreads();

    if (threadIdx.x == 0) {
        float v[KTOP]; int id[KTOP];
        #pragma unroll
        for (int i = 0; i < KTOP; i++) { v[i] = -3.402823466e38f; id[i] = 0; }
        #pragma unroll
        for (int c = 0; c < NCAND; c++)
            ins_n(ss[c], g_cand[row * NCAND + c], v, id, KTOP);
        float ssum = 0.f;
        #pragma unroll
        for (int i = 0; i < KTOP; i++) ssum += metrics[id[i]];
        if (phase == 0) g_partial[row] = ssum;
        else            out[row] = (g_partial[row] + ssum) * (1.f / (2.f * KTOP));
    }
}

// ---------------- launch ------------------------------------------------------
extern "C" void kernel_launch(void* const* d_in, const int* in_sizes, int n_in,
                              void* d_out, int out_size) {
    const float* f_content    = nullptr;
    const float* f_distorsion = nullptr;
    const float* sem_bank     = nullptr;
    const float* dst_bank     = nullptr;
    const float* metrics      = nullptr;
    for (int i = 0; i < n_in; i++) {
        switch (in_sizes[i]) {
            case B_Q * DIM_S:    f_content    = (const float*)d_in[i]; break;
            case B_Q * DIM_D:    f_distorsion = (const float*)d_in[i]; break;
            case N_BANK * DIM_S: sem_bank     = (const float*)d_in[i]; break;
            case N_BANK * DIM_D: dst_bank     = (const float*)d_in[i]; break;
            case N_BANK:         metrics      = (const float*)d_in[i]; break;
            default: break; // scalar K (=9) compiled in
        }
    }
    float* out = (float*)d_out;

    cudaFuncSetAttribute(gemm_hmma_kernel,
                         cudaFuncAttributeMaxDynamicSharedMemorySize, SMEM_TOTAL);

    dim3 grid(B_Q / TILE_M, (N_BANK + TILE_N - 1) / TILE_N);   // (2, 391), m-fastest
    dim3 selg(B_Q, NSEG);

    // semantic branch
    gemm_hmma_kernel<<<grid, 256, SMEM_TOTAL>>>(f_content, sem_bank, DIM_S);
    select_kernel<<<selg, 256>>>();
    rescore_kernel<<<B_Q, 256>>>(f_content, sem_bank, DIM_S, metrics, out, 0);

    // distorsion branch (reuses g_scores)
    gemm_hmma_kernel<<<grid, 256, SMEM_TOTAL>>>(f_distorsion, dst_bank, DIM_D);
    select_kernel<<<selg, 256>>>();
    rescore_kernel<<<B_Q, 256>>>(f_distorsion, dst_bank, DIM_D, metrics, out, 1);
}

// round 12
// speedup vs baseline: 4.5615x; 1.3365x over previous
#include <cuda_runtime.h>
#include <cuda_bf16.h>
#include <cstdint>
#include <cstddef>
#include <cfloat>

// Problem constants (fixed by setup_inputs).
#define B_Q    256
#define N_BANK 50000
#define DIM_S  4096
#define DIM_D  2048
#define KTOP   9

// GEMM tiling
#define TILE_M   128
#define TILE_N   128
#define T_STRIDE 80                 // bytes per bf16 tile row (64B data + 16B pad)
#define T_SIZE   (128 * T_STRIDE)   // 10240 bytes per tile
#define STAGE    (2 * T_SIZE)       // Ah, Bh (1-pass bf16)
#define OFF_INV  (2 * STAGE)        // 40960
#define SMEM_TOTAL (OFF_INV + 512)

// Candidate machinery
#define NSTRIPE      1564           // ceil(50048/32); last partially/fully invalid
#define NSTRIPE_PAD  1568
#define NCAND        16

// ---------------- static device scratch (no allocations allowed) -------------
__device__ __align__(128) float2 g_sel[(size_t)B_Q * NSTRIPE_PAD * 4];  // 12.9 MB
__device__ __align__(128) float  g_partial[B_Q];

// ---------------- PTX helpers -------------------------------------------------
__device__ __forceinline__ uint32_t smem_u32(const void* p) {
    uint32_t a;
    asm("{ .reg .u64 t; cvta.to.shared.u64 t, %1; cvt.u32.u64 %0, t; }" : "=r"(a) : "l"(p));
    return a;
}
__device__ __forceinline__ void sts64(uint32_t addr, uint32_t a, uint32_t b) {
    asm volatile("st.shared.v2.b32 [%0], {%1,%2};" :: "r"(addr), "r"(a), "r"(b));
}
#define LDSM4(r, addr) \
    asm volatile("ldmatrix.sync.aligned.m8n8.x4.shared.b16 {%0,%1,%2,%3}, [%4];" \
        : "=r"((r)[0]), "=r"((r)[1]), "=r"((r)[2]), "=r"((r)[3]) : "r"(addr))

#define MMA16816(d, a, b0, b1) \
    asm volatile("mma.sync.aligned.m16n8k16.row.col.f32.bf16.bf16.f32 " \
        "{%0,%1,%2,%3}, {%4,%5,%6,%7}, {%8,%9}, {%0,%1,%2,%3};" \
        : "+f"((d)[0]), "+f"((d)[1]), "+f"((d)[2]), "+f"((d)[3]) \
        : "r"((a)[0]), "r"((a)[1]), "r"((a)[2]), "r"((a)[3]), "r"(b0), "r"(b1))

// float4 -> two packed bf16x2 (low 16 bits = lower column)
__device__ __forceinline__ void cvt_hi(float4 v, uint32_t& h0, uint32_t& h1) {
    asm("cvt.rn.bf16x2.f32 %0, %1, %2;" : "=r"(h0) : "f"(v.y), "f"(v.x));
    asm("cvt.rn.bf16x2.f32 %0, %1, %2;" : "=r"(h1) : "f"(v.w), "f"(v.z));
}

// sorted depth-4 insert (descending)
__device__ __forceinline__ void ins4(float s, int n, float* v, int* id) {
    if (s <= v[3]) return;
    v[3] = s; id[3] = n;
    for (int q = 3; q > 0; q--) {
        if (v[q] > v[q - 1]) {
            float tv = v[q]; v[q] = v[q - 1]; v[q - 1] = tv;
            int   ti = id[q]; id[q] = id[q - 1]; id[q - 1] = ti;
        } else break;
    }
}
// generic sorted insert (descending)
__device__ __forceinline__ void ins_n(float s, int n, float* v, int* id, int depth) {
    if (s <= v[depth - 1]) return;
    v[depth - 1] = s; id[depth - 1] = n;
    for (int q = depth - 1; q > 0; q--) {
        if (v[q] > v[q - 1]) {
            float tv = v[q]; v[q] = v[q - 1]; v[q - 1] = tv;
            int   ti = id[q]; id[q] = id[q - 1]; id[q - 1] = ti;
        } else break;
    }
}

// ---------------- 1) 1-pass bf16 HMMA GEMM + fused invnorm + fused top-4 ------
// For each (row m, 32-col stripe): writes approx-score top-4 (val, idx) pairs.
__global__ __launch_bounds__(256, 2)
void gemm_hmma_kernel(const float* __restrict__ A,
                      const float* __restrict__ Bank,
                      int K)
{
    extern __shared__ char smem[];
    const uint32_t sb = smem_u32(smem);
    const int tid = threadIdx.x;
    const int w = tid >> 5, l = tid & 31;
    const int wm = w >> 2, wn = w & 3;           // warp grid 2 x 4
    const int m0 = blockIdx.x * TILE_M;
    const int n0 = blockIdx.y * TILE_N;
    const int NC = K >> 5;

    // ---- coalesced loader: 8 threads/row, one float4 each (full 128B line) --
    const int lrow8 = tid >> 3;                  // 0..31 (row within 32-group)
    const int lc8   = (tid & 7) << 2;            // fp32 col 0,4,...,28
    const float* Apt[4];
    const float* Bpt[4];
    bool bokk[4];
    uint32_t so[4];
    #pragma unroll
    for (int it = 0; it < 4; it++) {
        const int r = lrow8 + it * 32;
        Apt[it] = A + (size_t)(m0 + r) * K + lc8;
        const int br = n0 + r;
        bokk[it] = br < N_BANK;
        Bpt[it] = Bank + (size_t)(bokk[it] ? br : 0) * K + lc8;
        so[it] = (uint32_t)(r * T_STRIDE + (tid & 7) * 8);
    }

    // ldmatrix lane offsets (tile layout unchanged)
    const uint32_t a_loff = (uint32_t)((wm * 64 + (l & 15)) * T_STRIDE + (l >> 4) * 16);
    const uint32_t b_loff = (uint32_t)((wn * 32 + l) * T_STRIDE);

    float acc[4][4][4];
    #pragma unroll
    for (int i = 0; i < 4; i++)
        #pragma unroll
        for (int j = 0; j < 4; j++)
            #pragma unroll
            for (int e = 0; e < 4; e++) acc[i][j][e] = 0.f;

    float bsum[4] = {0.f, 0.f, 0.f, 0.f};

    // prologue: chunk 0 -> stage 0
    {
        #pragma unroll
        for (int it = 0; it < 4; it++) {
            float4 av = *reinterpret_cast<const float4*>(Apt[it]);
            float4 bv = bokk[it] ? *reinterpret_cast<const float4*>(Bpt[it])
                                 : make_float4(0.f, 0.f, 0.f, 0.f);
            bsum[it] += bv.x * bv.x + bv.y * bv.y + bv.z * bv.z + bv.w * bv.w;
            uint32_t h0, h1;
            cvt_hi(av, h0, h1); sts64(sb + so[it], h0, h1);
            cvt_hi(bv, h0, h1); sts64(sb + T_SIZE + so[it], h0, h1);
        }
    }
    __syncthreads();

    #pragma unroll 1
    for (int ch = 0; ch < NC; ch++) {
        const int cur = ch & 1;
        const uint32_t base = sb + (uint32_t)cur * STAGE;

        float4 av[4], bv[4];
        const bool pf = (ch + 1 < NC);
        if (pf) {
            const int k0 = (ch + 1) << 5;
            #pragma unroll
            for (int it = 0; it < 4; it++)
                av[it] = *reinterpret_cast<const float4*>(Apt[it] + k0);
            #pragma unroll
            for (int it = 0; it < 4; it++)
                bv[it] = bokk[it] ? *reinterpret_cast<const float4*>(Bpt[it] + k0)
                                  : make_float4(0.f, 0.f, 0.f, 0.f);
        }

        // MMA on stage `cur`: 2 k16-steps
        #pragma unroll
        for (int kc = 0; kc < 2; kc++) {
            const uint32_t kb = (uint32_t)kc * 32;
            uint32_t ah[4][4], bh[2][4];
            #pragma unroll
            for (int mi = 0; mi < 4; mi++)
                LDSM4(ah[mi], base + a_loff + (uint32_t)mi * (16 * T_STRIDE) + kb);
            LDSM4(bh[0], base + T_SIZE + b_loff + kb);
            LDSM4(bh[1], base + T_SIZE + b_loff + kb + 16);

            #pragma unroll
            for (int mi = 0; mi < 4; mi++)
                #pragma unroll
                for (int ni = 0; ni < 4; ni++)
                    MMA16816(acc[mi][ni], ah[mi], bh[0][ni], bh[1][ni]);
        }

        if (pf) {
            const uint32_t st = sb + (uint32_t)(cur ^ 1) * STAGE;
            #pragma unroll
            for (int it = 0; it < 4; it++) {
                bsum[it] += bv[it].x * bv[it].x + bv[it].y * bv[it].y +
                            bv[it].z * bv[it].z + bv[it].w * bv[it].w;
                uint32_t h0, h1;
                cvt_hi(av[it], h0, h1); sts64(st + so[it], h0, h1);
                cvt_hi(bv[it], h0, h1); sts64(st + T_SIZE + so[it], h0, h1);
            }
        }
        __syncthreads();
    }

    // ---- per-row inverse norms: reduce across the 8 lanes of each row group --
    float* s_inv = reinterpret_cast<float*>(smem + OFF_INV);
    #pragma unroll
    for (int it = 0; it < 4; it++) {
        float v = bsum[it];
        v += __shfl_xor_sync(0xffffffffu, v, 1);
        v += __shfl_xor_sync(0xffffffffu, v, 2);
        v += __shfl_xor_sync(0xffffffffu, v, 4);
        if ((tid & 7) == 0)
            s_inv[lrow8 + it * 32] = (v > 0.f) ? rsqrtf(v) : 0.f;
    }
    __syncthreads();

    // ---- epilogue: per-(row, 32-col stripe) top-4 of scaled scores ----------
    {
        const int qr = l >> 2;
        const int qc = (l & 3) * 2;
        const int stripe = blockIdx.y * 4 + wn;
        #pragma unroll
        for (int mi = 0; mi < 4; mi++) {
            #pragma unroll
            for (int h = 0; h < 2; h++) {
                float v[4]; int id[4];
                #pragma unroll
                for (int j = 0; j < 4; j++) { v[j] = -FLT_MAX; id[j] = 0; }
                #pragma unroll
                for (int ni = 0; ni < 4; ni++) {
                    const int nloc = wn * 32 + ni * 8 + qc;
                    const int ng = n0 + nloc;
                    const float* d = acc[mi][ni];
                    float s0 = (ng     < N_BANK) ? d[2 * h]     * s_inv[nloc]     : -FLT_MAX;
                    float s1 = (ng + 1 < N_BANK) ? d[2 * h + 1] * s_inv[nloc + 1] : -FLT_MAX;
                    ins4(s0, ng,     v, id);
                    ins4(s1, ng + 1, v, id);
                }
                // quad merge (lanes 4q..4q+3 hold the same row)
                #pragma unroll
                for (int o = 1; o <= 2; o <<= 1) {
                    float tv[4]; int ti[4];
                    #pragma unroll
                    for (int j = 0; j < 4; j++) { tv[j] = v[j]; ti[j] = id[j]; }
                    #pragma unroll
                    for (int j = 0; j < 4; j++) {
                        float ov = __shfl_xor_sync(0xffffffffu, tv[j], o);
                        int   oi = __shfl_xor_sync(0xffffffffu, ti[j], o);
                        ins4(ov, oi, v, id);
                    }
                }
                if ((l & 3) == 0) {
                    const int row = m0 + wm * 64 + mi * 16 + qr + 8 * h;
                    float2* dst = g_sel + ((size_t)row * NSTRIPE_PAD + stripe) * 4;
                    #pragma unroll
                    for (int j = 0; j < 4; j++)
                        dst[j] = make_float2(v[j], __int_as_float(id[j]));
                }
            }
        }
    }
}

// ---------------- 2) fused final select (top-16) + exact rescore + top-9 ------
__global__ void finalsel_kernel(const float* __restrict__ A,
                                const float* __restrict__ Bank,
                                int K,
                                const float* __restrict__ metrics,
                                float* __restrict__ out,
                                int phase)
{
    __shared__ float sv[256 * 4];
    __shared__ int   si[256 * 4];
    __shared__ float sv2[32 * 8];
    __shared__ int   si2[32 * 8];
    __shared__ float cv[NCAND];
    __shared__ int   ci[NCAND];
    __shared__ float ss[NCAND];

    const int row = blockIdx.x;
    const int tid = threadIdx.x;

    // phase 1: per-thread top-4 over strided entries (2 entries per float4)
    const float4* base4 = reinterpret_cast<const float4*>(
        g_sel + (size_t)row * NSTRIPE_PAD * 4);
    const int nf4 = NSTRIPE * 4 / 2;      // 3128

    float v[4]; int id[4];
    #pragma unroll
    for (int j = 0; j < 4; j++) { v[j] = -FLT_MAX; id[j] = 0; }
    for (int i = tid; i < nf4; i += 256) {
        float4 x = base4[i];
        ins4(x.x, __float_as_int(x.y), v, id);
        ins4(x.z, __float_as_int(x.w), v, id);
    }
    #pragma unroll
    for (int j = 0; j < 4; j++) { sv[tid * 4 + j] = v[j]; si[tid * 4 + j] = id[j]; }
    __syncthreads();

    // phase 2: warp-0 funnel 1024 -> 256 (strided so one thread's 4 spread out)
    if (tid < 32) {
        float mv[8]; int mi[8];
        #pragma unroll
        for (int j = 0; j < 8; j++) { mv[j] = -FLT_MAX; mi[j] = 0; }
        for (int e = tid; e < 1024; e += 32)
            ins_n(sv[e], si[e], mv, mi, 8);
        #pragma unroll
        for (int j = 0; j < 8; j++) { sv2[tid * 8 + j] = mv[j]; si2[tid * 8 + j] = mi[j]; }
    }
    __syncthreads();

    // phase 3: thread 0 -> global top-16 candidates
    if (tid == 0) {
        float mv[NCAND]; int mi[NCAND];
        #pragma unroll
        for (int j = 0; j < NCAND; j++) { mv[j] = -FLT_MAX; mi[j] = 0; }
        for (int e = 0; e < 256; e++)
            ins_n(sv2[e], si2[e], mv, mi, NCAND);
        #pragma unroll
        for (int j = 0; j < NCAND; j++) { cv[j] = mv[j]; ci[j] = mi[j]; }
    }
    __syncthreads();

    // phase 4: exact fp32 rescore of 16 candidates (2 per warp)
    {
        const int w = tid >> 5, l = tid & 31;
        const float4* q4 = reinterpret_cast<const float4*>(A + (size_t)row * K);
        const int kv = K >> 2;
        for (int c = w; c < NCAND; c += 8) {
            const int idx = ci[c];
            const float4* b4 = reinterpret_cast<const float4*>(Bank + (size_t)idx * K);
            float dot = 0.f, bsq = 0.f;
            for (int i = l; i < kv; i += 32) {
                float4 b = b4[i], q = q4[i];
                dot += q.x * b.x + q.y * b.y + q.z * b.z + q.w * b.w;
                bsq += b.x * b.x + b.y * b.y + b.z * b.z + b.w * b.w;
            }
            #pragma unroll
            for (int o = 16; o; o >>= 1) {
                dot += __shfl_xor_sync(0xffffffffu, dot, o);
                bsq += __shfl_xor_sync(0xffffffffu, bsq, o);
            }
            if (l == 0) ss[c] = dot * rsqrtf(bsq);
        }
    }
    __syncthreads();

    // phase 5: exact top-9 + metrics mean
    if (tid == 0) {
        float v9[KTOP]; int id9[KTOP];
        #pragma unroll
        for (int j = 0; j < KTOP; j++) { v9[j] = -FLT_MAX; id9[j] = 0; }
        #pragma unroll
        for (int c = 0; c < NCAND; c++)
            ins_n(ss[c], ci[c], v9, id9, KTOP);
        float ssum = 0.f;
        #pragma unroll
        for (int j = 0; j < KTOP; j++) ssum += metrics[id9[j]];
        if (phase == 0) g_partial[row] = ssum;
        else            out[row] = (g_partial[row] + ssum) * (1.f / (2.f * KTOP));
    }
}

// ---------------- launch ------------------------------------------------------
extern "C" void kernel_launch(void* const* d_in, const int* in_sizes, int n_in,
                              void* d_out, int out_size) {
    const float* f_content    = nullptr;
    const float* f_distorsion = nullptr;
    const float* sem_bank     = nullptr;
    const float* dst_bank     = nullptr;
    const float* metrics      = nullptr;
    for (int i = 0; i < n_in; i++) {
        switch (in_sizes[i]) {
            case B_Q * DIM_S:    f_content    = (const float*)d_in[i]; break;
            case B_Q * DIM_D:    f_distorsion = (const float*)d_in[i]; break;
            case N_BANK * DIM_S: sem_bank     = (const float*)d_in[i]; break;
            case N_BANK * DIM_D: dst_bank     = (const float*)d_in[i]; break;
            case N_BANK:         metrics      = (const float*)d_in[i]; break;
            default: break; // scalar K (=9) compiled in
        }
    }
    float* out = (float*)d_out;

    cudaFuncSetAttribute(gemm_hmma_kernel,
                         cudaFuncAttributeMaxDynamicSharedMemorySize, SMEM_TOTAL);

    dim3 grid(B_Q / TILE_M, (N_BANK + TILE_N - 1) / TILE_N);   // (2, 391), m-fastest

    // semantic branch
    gemm_hmma_kernel<<<grid, 256, SMEM_TOTAL>>>(f_content, sem_bank, DIM_S);
    finalsel_kernel<<<B_Q, 256>>>(f_content, sem_bank, DIM_S, metrics, out, 0);

    // distorsion branch (reuses g_sel)
    gemm_hmma_kernel<<<grid, 256, SMEM_TOTAL>>>(f_distorsion, dst_bank, DIM_D);
    finalsel_kernel<<<B_Q, 256>>>(f_distorsion, dst_bank, DIM_D, metrics, out, 1);
}